// round 1
// baseline (speedup 1.0000x reference)
#include <cuda_runtime.h>

// out[b,p,:] = { c1*c2*c3, c0*c1, c0*c1*c2, c0*c1*c2*c3 }, c_i = cos(patches[b,p,i]).
// RZ params provably do not affect the output (unit phases cancel in |amp|^2).

__global__ void quantum_patch_kernel(const float4* __restrict__ in,
                                     float4* __restrict__ out,
                                     int n_patches) {
    int i = blockIdx.x * blockDim.x + threadIdx.x;
    if (i < n_patches) {
        float4 x = in[i];
        float c0 = __cosf(x.x);
        float c1 = __cosf(x.y);
        float c2 = __cosf(x.z);
        float c3 = __cosf(x.w);
        float c01  = c0 * c1;
        float c012 = c01 * c2;
        float4 o;
        o.x = c1 * c2 * c3;
        o.y = c01;
        o.z = c012;
        o.w = c012 * c3;
        out[i] = o;
    }
}

extern "C" void kernel_launch(void* const* d_in, const int* in_sizes, int n_in,
                              void* d_out, int out_size) {
    const float4* patches = (const float4*)d_in[0];   // (256, 2048, 4) f32
    float4* out = (float4*)d_out;                     // (256, 8192) f32 — same layout
    int n_patches = in_sizes[0] / 4;                  // 524288
    int threads = 256;
    int blocks = (n_patches + threads - 1) / threads;
    quantum_patch_kernel<<<blocks, threads>>>(patches, out, n_patches);
}